// round 9
// baseline (speedup 1.0000x reference)
#include <cuda_runtime.h>
#include <cstdint>
#include <cstddef>

// ---------------- problem constants ----------------
static constexpr int Bm = 1024;     // batch rows
static constexpr int Dk = 512;      // feature dim (K)
static constexpr int Cn = 100000;   // classes (N)
static constexpr float S_s = 30.0f;
static constexpr float M_m = 0.4f;

// ---------------- device scratch (no runtime allocation allowed) ----------------
__device__ float g_Xn[Bm * Dk];                       // normalized x
__device__ float g_winv[Cn];                          // 1 / ||W[:,c]||
__device__ float g_rowsum[Bm];                        // sum_c exp(S*cos)
__device__ float g_cos_scratch[(size_t)Bm * (size_t)Cn]; // only used if d_out can't hold cossim

// ---------------- helpers ----------------
__device__ __forceinline__ float to_tf32(float x) {
    uint32_t u;
    asm("cvt.rna.tf32.f32 %0, %1;" : "=r"(u) : "f"(x));
    return __uint_as_float(u);
}

__device__ __forceinline__ void mma8(float* d, const uint32_t* a, const uint32_t* b) {
    asm volatile(
        "mma.sync.aligned.m16n8k8.row.col.f32.tf32.tf32.f32 "
        "{%0,%1,%2,%3}, {%4,%5,%6,%7}, {%8,%9}, {%0,%1,%2,%3};\n"
        : "+f"(d[0]), "+f"(d[1]), "+f"(d[2]), "+f"(d[3])
        : "r"(a[0]), "r"(a[1]), "r"(a[2]), "r"(a[3]), "r"(b[0]), "r"(b[1]));
}

// ---------------- kernel 1: L2-normalize rows of x; zero rowsum ----------------
__global__ void normalize_x_kernel(const float* __restrict__ x) {
    const int b = blockIdx.x;           // 1024 blocks
    const int t = threadIdx.x;          // 128 threads
    float4 v = reinterpret_cast<const float4*>(x + (size_t)b * Dk)[t];
    float ss = v.x * v.x + v.y * v.y + v.z * v.z + v.w * v.w;
    #pragma unroll
    for (int o = 16; o > 0; o >>= 1) ss += __shfl_xor_sync(0xffffffffu, ss, o);
    __shared__ float ws[4];
    if ((t & 31) == 0) ws[t >> 5] = ss;
    __syncthreads();
    const float tot = ws[0] + ws[1] + ws[2] + ws[3];
    const float inv = 1.0f / fmaxf(sqrtf(tot), 1e-12f);
    float4 o4;
    o4.x = v.x * inv; o4.y = v.y * inv; o4.z = v.z * inv; o4.w = v.w * inv;
    reinterpret_cast<float4*>(g_Xn + (size_t)b * Dk)[t] = o4;
    if (t == 0) g_rowsum[b] = 0.0f;
}

// ---------------- kernel 2: per-column inverse norms of W ----------------
__global__ void wnorm_kernel(const float* __restrict__ Wp) {
    const int c = blockIdx.x * blockDim.x + threadIdx.x;
    if (c >= Cn) return;
    float ss = 0.0f;
    #pragma unroll 8
    for (int d = 0; d < Dk; ++d) {
        const float w = Wp[(size_t)d * Cn + c];
        ss = fmaf(w, w, ss);
    }
    g_winv[c] = 1.0f / fmaxf(sqrtf(ss), 1e-12f);
}

// ---------------- kernel 3: TF32 GEMM + fused AM-Softmax epilogue ----------------
#define BMT 128
#define BNT 128
#define BKT 16
#define LDA 20      // BK + 4  -> conflict-free A fragment loads
#define LDB 136     // BN + 8  -> conflict-free B fragment loads

__global__ void __launch_bounds__(256, 2)
gemm_cos_kernel(const float* __restrict__ Wp, float* __restrict__ outp) {
    __shared__ __align__(16) float As[2][BMT * LDA];
    __shared__ __align__(16) float Bs[2][BKT * LDB];

    float* __restrict__ outc = outp ? outp : g_cos_scratch;

    const int tid  = threadIdx.x;
    const int lane = tid & 31;
    const int g    = lane >> 2;
    const int t    = lane & 3;
    const int warp = tid >> 5;
    const int wm   = warp & 1;    // 2 warps in M
    const int wn   = warp >> 1;   // 4 warps in N
    const int bN   = blockIdx.x * BNT;
    const int bM   = blockIdx.y * BMT;

    // global-load coordinates (per thread)
    const int arow = tid >> 2;          // 0..63 (+64 for second chunk)
    const int ac4  = (tid & 3) * 4;     // k offset within BK
    const int bkr  = tid >> 5;          // 0..7  (+8 for second chunk)
    const int bc4  = (tid & 31) * 4;    // col offset within BN
    const int bcol = bN + bc4;
    const bool bvalid = (bcol < Cn);

    float acc[4][4][4];
    #pragma unroll
    for (int i = 0; i < 4; ++i)
        #pragma unroll
        for (int j = 0; j < 4; ++j)
            #pragma unroll
            for (int k = 0; k < 4; ++k) acc[i][j][k] = 0.0f;

    const float* Abase = g_Xn + (size_t)bM * Dk;

    float4 ra0, ra1, rb0, rb1;
    // prologue: load k-chunk 0
    ra0 = *reinterpret_cast<const float4*>(Abase + (size_t)arow * Dk + ac4);
    ra1 = *reinterpret_cast<const float4*>(Abase + (size_t)(arow + 64) * Dk + ac4);
    if (bvalid) {
        rb0 = *reinterpret_cast<const float4*>(Wp + (size_t)bkr * Cn + bcol);
        rb1 = *reinterpret_cast<const float4*>(Wp + (size_t)(bkr + 8) * Cn + bcol);
    } else {
        rb0 = make_float4(0.f, 0.f, 0.f, 0.f);
        rb1 = rb0;
    }
    // store into buffer 0 (with round-to-nearest tf32 conversion)
    {
        float4 c;
        c.x = to_tf32(ra0.x); c.y = to_tf32(ra0.y); c.z = to_tf32(ra0.z); c.w = to_tf32(ra0.w);
        *reinterpret_cast<float4*>(&As[0][arow * LDA + ac4]) = c;
        c.x = to_tf32(ra1.x); c.y = to_tf32(ra1.y); c.z = to_tf32(ra1.z); c.w = to_tf32(ra1.w);
        *reinterpret_cast<float4*>(&As[0][(arow + 64) * LDA + ac4]) = c;
        c.x = to_tf32(rb0.x); c.y = to_tf32(rb0.y); c.z = to_tf32(rb0.z); c.w = to_tf32(rb0.w);
        *reinterpret_cast<float4*>(&Bs[0][bkr * LDB + bc4]) = c;
        c.x = to_tf32(rb1.x); c.y = to_tf32(rb1.y); c.z = to_tf32(rb1.z); c.w = to_tf32(rb1.w);
        *reinterpret_cast<float4*>(&Bs[0][(bkr + 8) * LDB + bc4]) = c;
    }
    __syncthreads();

    const int nIter = Dk / BKT;   // 32
    for (int it = 0; it < nIter; ++it) {
        const int cur = it & 1;
        if (it + 1 < nIter) {
            const int kb = (it + 1) * BKT;
            ra0 = *reinterpret_cast<const float4*>(Abase + (size_t)arow * Dk + kb + ac4);
            ra1 = *reinterpret_cast<const float4*>(Abase + (size_t)(arow + 64) * Dk + kb + ac4);
            if (bvalid) {
                rb0 = *reinterpret_cast<const float4*>(Wp + (size_t)(kb + bkr) * Cn + bcol);
                rb1 = *reinterpret_cast<const float4*>(Wp + (size_t)(kb + bkr + 8) * Cn + bcol);
            }
        }

        // compute on buffer `cur`
        #pragma unroll
        for (int kk = 0; kk < BKT; kk += 8) {
            uint32_t af[4][4];
            uint32_t bf[4][2];
            #pragma unroll
            for (int mt = 0; mt < 4; ++mt) {
                const int m = wm * 64 + mt * 16 + g;
                const float* A0 = &As[cur][m * LDA + kk + t];
                af[mt][0] = __float_as_uint(A0[0]);
                af[mt][1] = __float_as_uint(A0[8 * LDA]);
                af[mt][2] = __float_as_uint(A0[4]);
                af[mt][3] = __float_as_uint(A0[8 * LDA + 4]);
            }
            #pragma unroll
            for (int nt = 0; nt < 4; ++nt) {
                const int n = wn * 32 + nt * 8 + g;
                const float* B0 = &Bs[cur][(kk + t) * LDB + n];
                bf[nt][0] = __float_as_uint(B0[0]);
                bf[nt][1] = __float_as_uint(B0[4 * LDB]);
            }
            #pragma unroll
            for (int mt = 0; mt < 4; ++mt)
                #pragma unroll
                for (int nt = 0; nt < 4; ++nt)
                    mma8(acc[mt][nt], af[mt], bf[nt]);
        }

        if (it + 1 < nIter) {
            const int nxt = cur ^ 1;
            float4 c;
            c.x = to_tf32(ra0.x); c.y = to_tf32(ra0.y); c.z = to_tf32(ra0.z); c.w = to_tf32(ra0.w);
            *reinterpret_cast<float4*>(&As[nxt][arow * LDA + ac4]) = c;
            c.x = to_tf32(ra1.x); c.y = to_tf32(ra1.y); c.z = to_tf32(ra1.z); c.w = to_tf32(ra1.w);
            *reinterpret_cast<float4*>(&As[nxt][(arow + 64) * LDA + ac4]) = c;
            c.x = to_tf32(rb0.x); c.y = to_tf32(rb0.y); c.z = to_tf32(rb0.z); c.w = to_tf32(rb0.w);
            *reinterpret_cast<float4*>(&Bs[nxt][bkr * LDB + bc4]) = c;
            c.x = to_tf32(rb1.x); c.y = to_tf32(rb1.y); c.z = to_tf32(rb1.z); c.w = to_tf32(rb1.w);
            *reinterpret_cast<float4*>(&Bs[nxt][(bkr + 8) * LDB + bc4]) = c;
            __syncthreads();
        }
    }

    // -------- fused epilogue: scale by 1/||w_c||, clip, store, accumulate exp-sums --------
    float rsum[4][2];
    #pragma unroll
    for (int mt = 0; mt < 4; ++mt) { rsum[mt][0] = 0.0f; rsum[mt][1] = 0.0f; }

    #pragma unroll
    for (int mt = 0; mt < 4; ++mt) {
        const int gr0 = bM + wm * 64 + mt * 16 + g;
        #pragma unroll
        for (int nt = 0; nt < 4; ++nt) {
            const int gc = bN + wn * 32 + nt * 8 + t * 2;
            if (gc < Cn) {
                const float iw0 = g_winv[gc];
                const float iw1 = g_winv[gc + 1];
                float c0 = fminf(fmaxf(acc[mt][nt][0] * iw0, -1.0f), 1.0f);
                float c1 = fminf(fmaxf(acc[mt][nt][1] * iw1, -1.0f), 1.0f);
                float c2 = fminf(fmaxf(acc[mt][nt][2] * iw0, -1.0f), 1.0f);
                float c3 = fminf(fmaxf(acc[mt][nt][3] * iw1, -1.0f), 1.0f);
                *reinterpret_cast<float2*>(&outc[(size_t)gr0 * Cn + gc]) = make_float2(c0, c1);
                *reinterpret_cast<float2*>(&outc[(size_t)(gr0 + 8) * Cn + gc]) = make_float2(c2, c3);
                rsum[mt][0] += __expf(S_s * c0) + __expf(S_s * c1);
                rsum[mt][1] += __expf(S_s * c2) + __expf(S_s * c3);
            }
        }
    }
    // reduce across the 4 lanes of each quad (same rows, different columns)
    #pragma unroll
    for (int mt = 0; mt < 4; ++mt) {
        #pragma unroll
        for (int h = 0; h < 2; ++h) {
            float v = rsum[mt][h];
            v += __shfl_xor_sync(0xffffffffu, v, 1);
            v += __shfl_xor_sync(0xffffffffu, v, 2);
            if (t == 0) {
                const int gr = bM + wm * 64 + mt * 16 + g + h * 8;
                atomicAdd(&g_rowsum[gr], v);
            }
        }
    }
}

// ---------------- kernel 4: per-row loss, mean, scalar out ----------------
__global__ void loss_kernel(const float* __restrict__ cosp_param,
                            const int* __restrict__ lbl32,
                            float* __restrict__ loss_out) {
    const float* cosp = cosp_param ? cosp_param : g_cos_scratch;
    const int b = threadIdx.x;   // 1024 threads, one block

    // detect label dtype: int64 labels (< 2^31) have all-zero high words
    __shared__ int nz;
    if (b == 0) nz = 0;
    __syncthreads();
    if (b < 512 && lbl32[2 * b + 1] != 0) atomicOr(&nz, 1);
    __syncthreads();

    int label;
    if (nz == 0) label = (int)(reinterpret_cast<const long long*>(lbl32)[b]);
    else         label = lbl32[b];

    const float tgt  = cosp[(size_t)b * Cn + label];
    const float excl = g_rowsum[b] - __expf(S_s * tgt);   // same exp as the GEMM epilogue
    const float num  = S_s * (tgt - M_m);
    const float L    = num - logf(expf(num) + excl);

    // block reduce sum over 1024 threads
    float v = L;
    #pragma unroll
    for (int o = 16; o > 0; o >>= 1) v += __shfl_xor_sync(0xffffffffu, v, o);
    __shared__ float red[32];
    if ((b & 31) == 0) red[b >> 5] = v;
    __syncthreads();
    if (b < 32) {
        float w = red[b];
        #pragma unroll
        for (int o = 16; o > 0; o >>= 1) w += __shfl_xor_sync(0xffffffffu, w, o);
        if (b == 0) loss_out[0] = -(w / (float)Bm);
    }
}

// ---------------- launch ----------------
extern "C" void kernel_launch(void* const* d_in, const int* in_sizes, int n_in,
                              void* d_out, int out_size) {
    const float* x   = (const float*)d_in[0];
    const float* W   = (const float*)d_in[1];
    const int*   lbl = (const int*)d_in[2];
    float* out = (float*)d_out;

    const long long BC = (long long)Bm * (long long)Cn;   // 102,400,000
    const bool cos_in_out = ((long long)out_size >= BC);

    normalize_x_kernel<<<Bm, 128>>>(x);
    wnorm_kernel<<<(Cn + 255) / 256, 256>>>(W);

    dim3 gg((Cn + BNT - 1) / BNT, Bm / BMT);   // (782, 8)
    gemm_cos_kernel<<<gg, 256>>>(W, cos_in_out ? out : nullptr);

    if (!cos_in_out) {
        // output holds only the loss
        if (out_size >= 1) loss_kernel<<<1, Bm>>>(nullptr, lbl, out);
    } else if ((long long)out_size >= BC + 1) {
        loss_kernel<<<1, Bm>>>(out, lbl, out + BC);
    }
}

// round 11
// speedup vs baseline: 1.0100x; 1.0100x over previous
#include <cuda_runtime.h>
#include <cstdint>
#include <cstddef>

// ---------------- problem constants ----------------
static constexpr int Bm = 1024;     // batch rows
static constexpr int Dk = 512;      // feature dim (K)
static constexpr int Cn = 100000;   // classes (N)
static constexpr float S_s = 30.0f;
static constexpr float M_m = 0.4f;

// ---------------- device scratch (no runtime allocation allowed) ----------------
__device__ float g_Xn[Bm * Dk];                       // normalized x
__device__ float g_winv[Cn];                          // 1 / ||W[:,c]||
__device__ float g_rowsum[Bm];                        // sum_c exp(S*cos)
__device__ float g_cos_scratch[(size_t)Bm * (size_t)Cn]; // only used if d_out can't hold cossim

// ---------------- helpers ----------------
__device__ __forceinline__ float to_tf32(float x) {
    uint32_t u;
    asm("cvt.rna.tf32.f32 %0, %1;" : "=r"(u) : "f"(x));
    return __uint_as_float(u);
}

__device__ __forceinline__ void mma8(float* d, const uint32_t* a, const uint32_t* b) {
    asm volatile(
        "mma.sync.aligned.m16n8k8.row.col.f32.tf32.tf32.f32 "
        "{%0,%1,%2,%3}, {%4,%5,%6,%7}, {%8,%9}, {%0,%1,%2,%3};\n"
        : "+f"(d[0]), "+f"(d[1]), "+f"(d[2]), "+f"(d[3])
        : "r"(a[0]), "r"(a[1]), "r"(a[2]), "r"(a[3]), "r"(b[0]), "r"(b[1]));
}

// ---------------- pad kernel (shifts ncu -s 5 -c 1 capture onto the GEMM) ----
__global__ void pad_kernel() {}

// ---------------- kernel 1: L2-normalize rows of x; zero rowsum ----------------
__global__ void normalize_x_kernel(const float* __restrict__ x) {
    const int b = blockIdx.x;           // 1024 blocks
    const int t = threadIdx.x;          // 128 threads
    float4 v = reinterpret_cast<const float4*>(x + (size_t)b * Dk)[t];
    float ss = v.x * v.x + v.y * v.y + v.z * v.z + v.w * v.w;
    #pragma unroll
    for (int o = 16; o > 0; o >>= 1) ss += __shfl_xor_sync(0xffffffffu, ss, o);
    __shared__ float ws[4];
    if ((t & 31) == 0) ws[t >> 5] = ss;
    __syncthreads();
    const float tot = ws[0] + ws[1] + ws[2] + ws[3];
    const float inv = 1.0f / fmaxf(sqrtf(tot), 1e-12f);
    float4 o4;
    o4.x = v.x * inv; o4.y = v.y * inv; o4.z = v.z * inv; o4.w = v.w * inv;
    reinterpret_cast<float4*>(g_Xn + (size_t)b * Dk)[t] = o4;
    if (t == 0) g_rowsum[b] = 0.0f;
}

// ---------------- kernel 2: per-column inverse norms of W ----------------
__global__ void wnorm_kernel(const float* __restrict__ Wp) {
    const int c = blockIdx.x * blockDim.x + threadIdx.x;
    if (c >= Cn) return;
    float ss = 0.0f;
    #pragma unroll 8
    for (int d = 0; d < Dk; ++d) {
        const float w = Wp[(size_t)d * Cn + c];
        ss = fmaf(w, w, ss);
    }
    g_winv[c] = 1.0f / fmaxf(sqrtf(ss), 1e-12f);
}

// ---------------- kernel 3: TF32 GEMM + fused AM-Softmax epilogue ----------------
#define BMT 128
#define BNT 128
#define BKT 16
#define LDA 20      // BK + 4  -> conflict-free A fragment loads
#define LDB 136     // BN + 8  -> conflict-free B fragment loads

__global__ void __launch_bounds__(256, 2)
gemm_cos_kernel(const float* __restrict__ Wp, float* __restrict__ outp) {
    __shared__ __align__(16) float As[2][BMT * LDA];
    __shared__ __align__(16) float Bs[2][BKT * LDB];

    float* __restrict__ outc = outp ? outp : g_cos_scratch;

    const int tid  = threadIdx.x;
    const int lane = tid & 31;
    const int g    = lane >> 2;
    const int t    = lane & 3;
    const int warp = tid >> 5;
    const int wm   = warp & 1;    // 2 warps in M
    const int wn   = warp >> 1;   // 4 warps in N
    // GRID SWAP vs R9: x = M-block (8, fast), y = N-block (782).
    // Consecutive CTAs now cover all 8 M-blocks of one N-tile, so each
    // 256KB W tile is read from DRAM once and shared via L2 (8x less W traffic).
    const int bN   = blockIdx.y * BNT;
    const int bM   = blockIdx.x * BMT;

    // global-load coordinates (per thread)
    const int arow = tid >> 2;          // 0..63 (+64 for second chunk)
    const int ac4  = (tid & 3) * 4;     // k offset within BK
    const int bkr  = tid >> 5;          // 0..7  (+8 for second chunk)
    const int bc4  = (tid & 31) * 4;    // col offset within BN
    const int bcol = bN + bc4;
    const bool bvalid = (bcol < Cn);

    float acc[4][4][4];
    #pragma unroll
    for (int i = 0; i < 4; ++i)
        #pragma unroll
        for (int j = 0; j < 4; ++j)
            #pragma unroll
            for (int k = 0; k < 4; ++k) acc[i][j][k] = 0.0f;

    const float* Abase = g_Xn + (size_t)bM * Dk;

    float4 ra0, ra1, rb0, rb1;
    // prologue: load k-chunk 0
    ra0 = *reinterpret_cast<const float4*>(Abase + (size_t)arow * Dk + ac4);
    ra1 = *reinterpret_cast<const float4*>(Abase + (size_t)(arow + 64) * Dk + ac4);
    if (bvalid) {
        rb0 = *reinterpret_cast<const float4*>(Wp + (size_t)bkr * Cn + bcol);
        rb1 = *reinterpret_cast<const float4*>(Wp + (size_t)(bkr + 8) * Cn + bcol);
    } else {
        rb0 = make_float4(0.f, 0.f, 0.f, 0.f);
        rb1 = rb0;
    }
    // store into buffer 0 (with round-to-nearest tf32 conversion)
    {
        float4 c;
        c.x = to_tf32(ra0.x); c.y = to_tf32(ra0.y); c.z = to_tf32(ra0.z); c.w = to_tf32(ra0.w);
        *reinterpret_cast<float4*>(&As[0][arow * LDA + ac4]) = c;
        c.x = to_tf32(ra1.x); c.y = to_tf32(ra1.y); c.z = to_tf32(ra1.z); c.w = to_tf32(ra1.w);
        *reinterpret_cast<float4*>(&As[0][(arow + 64) * LDA + ac4]) = c;
        c.x = to_tf32(rb0.x); c.y = to_tf32(rb0.y); c.z = to_tf32(rb0.z); c.w = to_tf32(rb0.w);
        *reinterpret_cast<float4*>(&Bs[0][bkr * LDB + bc4]) = c;
        c.x = to_tf32(rb1.x); c.y = to_tf32(rb1.y); c.z = to_tf32(rb1.z); c.w = to_tf32(rb1.w);
        *reinterpret_cast<float4*>(&Bs[0][(bkr + 8) * LDB + bc4]) = c;
    }
    __syncthreads();

    const int nIter = Dk / BKT;   // 32
    for (int it = 0; it < nIter; ++it) {
        const int cur = it & 1;
        if (it + 1 < nIter) {
            const int kb = (it + 1) * BKT;
            ra0 = *reinterpret_cast<const float4*>(Abase + (size_t)arow * Dk + kb + ac4);
            ra1 = *reinterpret_cast<const float4*>(Abase + (size_t)(arow + 64) * Dk + kb + ac4);
            if (bvalid) {
                rb0 = *reinterpret_cast<const float4*>(Wp + (size_t)(kb + bkr) * Cn + bcol);
                rb1 = *reinterpret_cast<const float4*>(Wp + (size_t)(kb + bkr + 8) * Cn + bcol);
            }
        }

        // compute on buffer `cur`
        #pragma unroll
        for (int kk = 0; kk < BKT; kk += 8) {
            uint32_t af[4][4];
            uint32_t bf[4][2];
            #pragma unroll
            for (int mt = 0; mt < 4; ++mt) {
                const int m = wm * 64 + mt * 16 + g;
                const float* A0 = &As[cur][m * LDA + kk + t];
                af[mt][0] = __float_as_uint(A0[0]);
                af[mt][1] = __float_as_uint(A0[8 * LDA]);
                af[mt][2] = __float_as_uint(A0[4]);
                af[mt][3] = __float_as_uint(A0[8 * LDA + 4]);
            }
            #pragma unroll
            for (int nt = 0; nt < 4; ++nt) {
                const int n = wn * 32 + nt * 8 + g;
                const float* B0 = &Bs[cur][(kk + t) * LDB + n];
                bf[nt][0] = __float_as_uint(B0[0]);
                bf[nt][1] = __float_as_uint(B0[4 * LDB]);
            }
            #pragma unroll
            for (int mt = 0; mt < 4; ++mt)
                #pragma unroll
                for (int nt = 0; nt < 4; ++nt)
                    mma8(acc[mt][nt], af[mt], bf[nt]);
        }

        if (it + 1 < nIter) {
            const int nxt = cur ^ 1;
            float4 c;
            c.x = to_tf32(ra0.x); c.y = to_tf32(ra0.y); c.z = to_tf32(ra0.z); c.w = to_tf32(ra0.w);
            *reinterpret_cast<float4*>(&As[nxt][arow * LDA + ac4]) = c;
            c.x = to_tf32(ra1.x); c.y = to_tf32(ra1.y); c.z = to_tf32(ra1.z); c.w = to_tf32(ra1.w);
            *reinterpret_cast<float4*>(&As[nxt][(arow + 64) * LDA + ac4]) = c;
            c.x = to_tf32(rb0.x); c.y = to_tf32(rb0.y); c.z = to_tf32(rb0.z); c.w = to_tf32(rb0.w);
            *reinterpret_cast<float4*>(&Bs[nxt][bkr * LDB + bc4]) = c;
            c.x = to_tf32(rb1.x); c.y = to_tf32(rb1.y); c.z = to_tf32(rb1.z); c.w = to_tf32(rb1.w);
            *reinterpret_cast<float4*>(&Bs[nxt][(bkr + 8) * LDB + bc4]) = c;
            __syncthreads();
        }
    }

    // -------- fused epilogue: scale by 1/||w_c||, clip, store, accumulate exp-sums --------
    float rsum[4][2];
    #pragma unroll
    for (int mt = 0; mt < 4; ++mt) { rsum[mt][0] = 0.0f; rsum[mt][1] = 0.0f; }

    #pragma unroll
    for (int mt = 0; mt < 4; ++mt) {
        const int gr0 = bM + wm * 64 + mt * 16 + g;
        #pragma unroll
        for (int nt = 0; nt < 4; ++nt) {
            const int gc = bN + wn * 32 + nt * 8 + t * 2;
            if (gc < Cn) {
                const float iw0 = g_winv[gc];
                const float iw1 = g_winv[gc + 1];
                float c0 = fminf(fmaxf(acc[mt][nt][0] * iw0, -1.0f), 1.0f);
                float c1 = fminf(fmaxf(acc[mt][nt][1] * iw1, -1.0f), 1.0f);
                float c2 = fminf(fmaxf(acc[mt][nt][2] * iw0, -1.0f), 1.0f);
                float c3 = fminf(fmaxf(acc[mt][nt][3] * iw1, -1.0f), 1.0f);
                *reinterpret_cast<float2*>(&outc[(size_t)gr0 * Cn + gc]) = make_float2(c0, c1);
                *reinterpret_cast<float2*>(&outc[(size_t)(gr0 + 8) * Cn + gc]) = make_float2(c2, c3);
                rsum[mt][0] += __expf(S_s * c0) + __expf(S_s * c1);
                rsum[mt][1] += __expf(S_s * c2) + __expf(S_s * c3);
            }
        }
    }
    // reduce across the 4 lanes of each quad (same rows, different columns)
    #pragma unroll
    for (int mt = 0; mt < 4; ++mt) {
        #pragma unroll
        for (int h = 0; h < 2; ++h) {
            float v = rsum[mt][h];
            v += __shfl_xor_sync(0xffffffffu, v, 1);
            v += __shfl_xor_sync(0xffffffffu, v, 2);
            if (t == 0) {
                const int gr = bM + wm * 64 + mt * 16 + g + h * 8;
                atomicAdd(&g_rowsum[gr], v);
            }
        }
    }
}

// ---------------- kernel 4: per-row loss, mean, scalar out ----------------
__global__ void loss_kernel(const float* __restrict__ cosp_param,
                            const int* __restrict__ lbl32,
                            float* __restrict__ loss_out) {
    const float* cosp = cosp_param ? cosp_param : g_cos_scratch;
    const int b = threadIdx.x;   // 1024 threads, one block

    // detect label dtype: int64 labels (< 2^31) have all-zero high words
    __shared__ int nz;
    if (b == 0) nz = 0;
    __syncthreads();
    if (b < 512 && lbl32[2 * b + 1] != 0) atomicOr(&nz, 1);
    __syncthreads();

    int label;
    if (nz == 0) label = (int)(reinterpret_cast<const long long*>(lbl32)[b]);
    else         label = lbl32[b];

    const float tgt  = cosp[(size_t)b * Cn + label];
    const float excl = g_rowsum[b] - __expf(S_s * tgt);   // same exp as the GEMM epilogue
    const float num  = S_s * (tgt - M_m);
    const float L    = num - logf(expf(num) + excl);

    // block reduce sum over 1024 threads
    float v = L;
    #pragma unroll
    for (int o = 16; o > 0; o >>= 1) v += __shfl_xor_sync(0xffffffffu, v, o);
    __shared__ float red[32];
    if ((b & 31) == 0) red[b >> 5] = v;
    __syncthreads();
    if (b < 32) {
        float w = red[b];
        #pragma unroll
        for (int o = 16; o > 0; o >>= 1) w += __shfl_xor_sync(0xffffffffu, w, o);
        if (b == 0) loss_out[0] = -(w / (float)Bm);
    }
}

// ---------------- launch ----------------
extern "C" void kernel_launch(void* const* d_in, const int* in_sizes, int n_in,
                              void* d_out, int out_size) {
    const float* x   = (const float*)d_in[0];
    const float* W   = (const float*)d_in[1];
    const int*   lbl = (const int*)d_in[2];
    float* out = (float*)d_out;

    const long long BC = (long long)Bm * (long long)Cn;   // 102,400,000
    const bool cos_in_out = ((long long)out_size >= BC);

    normalize_x_kernel<<<Bm, 128>>>(x);
    wnorm_kernel<<<(Cn + 255) / 256, 256>>>(W);

    // three pad launches so ncu (-s 5 -c 1) captures the GEMM (launch index 5)
    pad_kernel<<<1, 32>>>();
    pad_kernel<<<1, 32>>>();
    pad_kernel<<<1, 32>>>();

    // grid: x = M-blocks (8, fast-moving), y = N-blocks (782) -> W tiles L2-shared
    dim3 gg(Bm / BMT, (Cn + BNT - 1) / BNT);   // (8, 782)
    gemm_cos_kernel<<<gg, 256>>>(W, cos_in_out ? out : nullptr);

    if (!cos_in_out) {
        // output holds only the loss
        if (out_size >= 1) loss_kernel<<<1, Bm>>>(nullptr, lbl, out);
    } else if ((long long)out_size >= BC + 1) {
        loss_kernel<<<1, Bm>>>(out, lbl, out + BC);
    }
}

// round 12
// speedup vs baseline: 1.2865x; 1.2737x over previous
#include <cuda_runtime.h>
#include <cuda_fp16.h>
#include <cstdint>
#include <cstddef>

// ---------------- problem constants ----------------
static constexpr int Bm = 1024;     // batch rows
static constexpr int Dk = 512;      // feature dim (K)
static constexpr int Cn = 100000;   // classes (N)
static constexpr float S_s = 30.0f;
static constexpr float M_m = 0.4f;

// ---------------- device scratch (no runtime allocation allowed) ----------------
__device__ __half g_Xh[Bm * Dk];                      // normalized x, fp16
__device__ float g_winv[Cn];                          // 1 / ||W[:,c]||
__device__ float g_rowsum[Bm];                        // sum_c exp(S*cos)
__device__ float g_cos_scratch[(size_t)Bm * (size_t)Cn]; // fallback cossim store

// ---------------- helpers ----------------
__device__ __forceinline__ uint32_t f2h2(float a, float b) {
    __half2 h = __floats2half2_rn(a, b);
    return *reinterpret_cast<uint32_t*>(&h);
}

__device__ __forceinline__ void mma16(float* d, const uint32_t* a, const uint32_t* b) {
    asm volatile(
        "mma.sync.aligned.m16n8k16.row.col.f32.f16.f16.f32 "
        "{%0,%1,%2,%3}, {%4,%5,%6,%7}, {%8,%9}, {%0,%1,%2,%3};\n"
        : "+f"(d[0]), "+f"(d[1]), "+f"(d[2]), "+f"(d[3])
        : "r"(a[0]), "r"(a[1]), "r"(a[2]), "r"(a[3]), "r"(b[0]), "r"(b[1]));
}

__device__ __forceinline__ void ldsm4(uint32_t* r, uint32_t addr) {
    asm volatile("ldmatrix.sync.aligned.m8n8.x4.shared.b16 {%0,%1,%2,%3}, [%4];"
                 : "=r"(r[0]), "=r"(r[1]), "=r"(r[2]), "=r"(r[3]) : "r"(addr));
}
__device__ __forceinline__ void ldsm2t(uint32_t* r, uint32_t addr) {
    asm volatile("ldmatrix.sync.aligned.m8n8.x2.trans.shared.b16 {%0,%1}, [%2];"
                 : "=r"(r[0]), "=r"(r[1]) : "r"(addr));
}

// swizzled byte offsets inside the smem tiles (16B cell granularity)
// A tile: 128 rows x 32 halfs (64B/row = 4 cells). Swizzle keeps ldmatrix
// (8 rows, fixed cell) conflict-free: cell ^= (row>>1)&3.
__device__ __forceinline__ int a_byte(int r, int c) {
    return r * 64 + ((c ^ ((r >> 1) & 3)) << 4);
}
// B tile: 32 rows (k) x 128 halfs (n) (256B/row = 16 cells). ldmatrix.trans
// reads 8 consecutive k-rows at one cell: cell ^= k&7.
__device__ __forceinline__ int b_byte(int k, int c) {
    return k * 256 + ((c ^ (k & 7)) << 4);
}

// ---------------- kernel 1: L2-normalize rows of x -> fp16; zero rowsum ----------
__global__ void normalize_x_kernel(const float* __restrict__ x) {
    const int b = blockIdx.x;           // 1024 blocks
    const int t = threadIdx.x;          // 128 threads
    float4 v = reinterpret_cast<const float4*>(x + (size_t)b * Dk)[t];
    float ss = v.x * v.x + v.y * v.y + v.z * v.z + v.w * v.w;
    #pragma unroll
    for (int o = 16; o > 0; o >>= 1) ss += __shfl_xor_sync(0xffffffffu, ss, o);
    __shared__ float ws[4];
    if ((t & 31) == 0) ws[t >> 5] = ss;
    __syncthreads();
    const float tot = ws[0] + ws[1] + ws[2] + ws[3];
    const float inv = 1.0f / fmaxf(sqrtf(tot), 1e-12f);
    uint2 st;
    st.x = f2h2(v.x * inv, v.y * inv);
    st.y = f2h2(v.z * inv, v.w * inv);
    reinterpret_cast<uint2*>(g_Xh + (size_t)b * Dk)[t] = st;
    if (t == 0) g_rowsum[b] = 0.0f;
}

// ---------------- kernel 2: per-column inverse norms of W ----------------
__global__ void wnorm_kernel(const float* __restrict__ Wp) {
    const int c = blockIdx.x * blockDim.x + threadIdx.x;
    if (c >= Cn) return;
    float ss = 0.0f;
    #pragma unroll 8
    for (int d = 0; d < Dk; ++d) {
        const float w = Wp[(size_t)d * Cn + c];
        ss = fmaf(w, w, ss);
    }
    g_winv[c] = 1.0f / fmaxf(sqrtf(ss), 1e-12f);
}

// ---------------- kernel 3: fp16 GEMM (m16n8k16) + fused AM-Softmax epilogue ------
#define BMT 128
#define BNT 128
#define BKT 32
// NCHUNK = 512/32 = 16

__global__ void __launch_bounds__(256, 2)
gemm_cos_kernel(const float* __restrict__ Wp, float* __restrict__ outp) {
    __shared__ __align__(128) uint8_t As[2][BMT * 64];   // 128 rows x 32 halfs
    __shared__ __align__(128) uint8_t Bs[2][BKT * 256];  // 32 k-rows x 128 halfs

    float* __restrict__ outc = outp ? outp : g_cos_scratch;

    const int tid  = threadIdx.x;
    const int lane = tid & 31;
    const int g    = lane >> 2;
    const int t    = lane & 3;
    const int warp = tid >> 5;
    const int wm   = warp & 1;    // 2 warps in M (64 rows each)
    const int wn   = warp >> 1;   // 4 warps in N (32 cols each)
    const int bN   = blockIdx.y * BNT;
    const int bM   = blockIdx.x * BMT;

    const uint32_t sA[2] = { (uint32_t)__cvta_generic_to_shared(As[0]),
                             (uint32_t)__cvta_generic_to_shared(As[1]) };
    const uint32_t sB[2] = { (uint32_t)__cvta_generic_to_shared(Bs[0]),
                             (uint32_t)__cvta_generic_to_shared(Bs[1]) };

    // ---- global-load coordinates ----
    // A: thread owns row (tid>>1), 16 consecutive halfs (2 cells) at cell (tid&1)*2
    const int arow = tid >> 1;
    const int ac0  = (tid & 1) * 2;
    // B: thread owns k-row (tid>>3), 16 consecutive n (2 cells) at cell (tid&7)*2
    const int bk   = tid >> 3;
    const int bc0  = (tid & 7) * 2;
    const int bn0  = bN + bc0 * 8;
    const bool bvalid = (bn0 + 16 <= Cn);   // Cn % 16 == 0 -> all-or-nothing

    float acc[4][4][4];
    #pragma unroll
    for (int i = 0; i < 4; ++i)
        #pragma unroll
        for (int j = 0; j < 4; ++j)
            #pragma unroll
            for (int k = 0; k < 4; ++k) acc[i][j][k] = 0.0f;

    uint4 ra0, ra1;
    float4 rb[4];

    auto load_chunk = [&](int kc) {
        const __half* Ap = g_Xh + (size_t)(bM + arow) * Dk + kc + ac0 * 8;
        ra0 = *reinterpret_cast<const uint4*>(Ap);
        ra1 = *reinterpret_cast<const uint4*>(Ap + 8);
        if (bvalid) {
            const float* Bp = Wp + (size_t)(kc + bk) * Cn + bn0;
            rb[0] = reinterpret_cast<const float4*>(Bp)[0];
            rb[1] = reinterpret_cast<const float4*>(Bp)[1];
            rb[2] = reinterpret_cast<const float4*>(Bp)[2];
            rb[3] = reinterpret_cast<const float4*>(Bp)[3];
        } else {
            rb[0] = rb[1] = rb[2] = rb[3] = make_float4(0.f, 0.f, 0.f, 0.f);
        }
    };
    auto store_chunk = [&](int buf) {
        uint8_t* Ab = As[buf];
        uint8_t* Bb = Bs[buf];
        *reinterpret_cast<uint4*>(Ab + a_byte(arow, ac0))     = ra0;
        *reinterpret_cast<uint4*>(Ab + a_byte(arow, ac0 + 1)) = ra1;
        uint4 c0, c1;
        c0.x = f2h2(rb[0].x, rb[0].y); c0.y = f2h2(rb[0].z, rb[0].w);
        c0.z = f2h2(rb[1].x, rb[1].y); c0.w = f2h2(rb[1].z, rb[1].w);
        c1.x = f2h2(rb[2].x, rb[2].y); c1.y = f2h2(rb[2].z, rb[2].w);
        c1.z = f2h2(rb[3].x, rb[3].y); c1.w = f2h2(rb[3].z, rb[3].w);
        *reinterpret_cast<uint4*>(Bb + b_byte(bk, bc0))     = c0;
        *reinterpret_cast<uint4*>(Bb + b_byte(bk, bc0 + 1)) = c1;
    };

    // per-lane ldmatrix address components
    const int rl = lane & 15;     // row within 16-row tile
    const int cp = lane >> 4;     // k-half selector (cell +0 / +1)

    auto compute_chunk = [&](int buf) {
        const uint32_t sAb = sA[buf];
        const uint32_t sBb = sB[buf];
        #pragma unroll
        for (int ks = 0; ks < 2; ++ks) {
            uint32_t af[4][4];
            uint32_t bf[4][2];
            #pragma unroll
            for (int mt = 0; mt < 4; ++mt) {
                const int r = wm * 64 + mt * 16 + rl;
                const int c = ks * 2 + cp;
                ldsm4(af[mt], sAb + a_byte(r, c));
            }
            #pragma unroll
            for (int nt = 0; nt < 4; ++nt) {
                const int k = ks * 16 + rl;
                const int cell = wn * 4 + nt;
                ldsm2t(bf[nt], sBb + b_byte(k, cell));
            }
            #pragma unroll
            for (int mt = 0; mt < 4; ++mt)
                #pragma unroll
                for (int nt = 0; nt < 4; ++nt)
                    mma16(acc[mt][nt], af[mt], bf[nt]);
        }
    };

    // ---- double-buffered mainloop ----
    load_chunk(0);
    store_chunk(0);
    __syncthreads();

    const int nIter = Dk / BKT;   // 16
    for (int it = 0; it < nIter; ++it) {
        const int cur = it & 1;
        if (it + 1 < nIter) load_chunk((it + 1) * BKT);
        compute_chunk(cur);
        if (it + 1 < nIter) {
            store_chunk(cur ^ 1);
            __syncthreads();
        }
    }

    // -------- fused epilogue: scale by 1/||w_c||, clip, store, accumulate exp-sums ----
    float rsum[4][2];
    #pragma unroll
    for (int mt = 0; mt < 4; ++mt) { rsum[mt][0] = 0.0f; rsum[mt][1] = 0.0f; }

    #pragma unroll
    for (int mt = 0; mt < 4; ++mt) {
        const int gr0 = bM + wm * 64 + mt * 16 + g;
        #pragma unroll
        for (int nt = 0; nt < 4; ++nt) {
            const int gc = bN + wn * 32 + nt * 8 + t * 2;
            if (gc < Cn) {
                const float iw0 = g_winv[gc];
                const float iw1 = g_winv[gc + 1];
                float c0 = fminf(fmaxf(acc[mt][nt][0] * iw0, -1.0f), 1.0f);
                float c1 = fminf(fmaxf(acc[mt][nt][1] * iw1, -1.0f), 1.0f);
                float c2 = fminf(fmaxf(acc[mt][nt][2] * iw0, -1.0f), 1.0f);
                float c3 = fminf(fmaxf(acc[mt][nt][3] * iw1, -1.0f), 1.0f);
                *reinterpret_cast<float2*>(&outc[(size_t)gr0 * Cn + gc]) = make_float2(c0, c1);
                *reinterpret_cast<float2*>(&outc[(size_t)(gr0 + 8) * Cn + gc]) = make_float2(c2, c3);
                rsum[mt][0] += __expf(S_s * c0) + __expf(S_s * c1);
                rsum[mt][1] += __expf(S_s * c2) + __expf(S_s * c3);
            }
        }
    }
    #pragma unroll
    for (int mt = 0; mt < 4; ++mt) {
        #pragma unroll
        for (int h = 0; h < 2; ++h) {
            float v = rsum[mt][h];
            v += __shfl_xor_sync(0xffffffffu, v, 1);
            v += __shfl_xor_sync(0xffffffffu, v, 2);
            if (t == 0) {
                const int gr = bM + wm * 64 + mt * 16 + g + h * 8;
                atomicAdd(&g_rowsum[gr], v);
            }
        }
    }
}

// ---------------- kernel 4: per-row loss, mean, scalar out ----------------
__global__ void loss_kernel(const float* __restrict__ cosp_param,
                            const int* __restrict__ lbl32,
                            float* __restrict__ loss_out) {
    const float* cosp = cosp_param ? cosp_param : g_cos_scratch;
    const int b = threadIdx.x;   // 1024 threads, one block

    __shared__ int nz;
    if (b == 0) nz = 0;
    __syncthreads();
    if (b < 512 && lbl32[2 * b + 1] != 0) atomicOr(&nz, 1);
    __syncthreads();

    int label;
    if (nz == 0) label = (int)(reinterpret_cast<const long long*>(lbl32)[b]);
    else         label = lbl32[b];

    const float tgt  = cosp[(size_t)b * Cn + label];
    const float excl = g_rowsum[b] - __expf(S_s * tgt);
    const float num  = S_s * (tgt - M_m);
    const float L    = num - logf(expf(num) + excl);

    float v = L;
    #pragma unroll
    for (int o = 16; o > 0; o >>= 1) v += __shfl_xor_sync(0xffffffffu, v, o);
    __shared__ float red[32];
    if ((b & 31) == 0) red[b >> 5] = v;
    __syncthreads();
    if (b < 32) {
        float w = red[b];
        #pragma unroll
        for (int o = 16; o > 0; o >>= 1) w += __shfl_xor_sync(0xffffffffu, w, o);
        if (b == 0) loss_out[0] = -(w / (float)Bm);
    }
}

// ---------------- launch ----------------
extern "C" void kernel_launch(void* const* d_in, const int* in_sizes, int n_in,
                              void* d_out, int out_size) {
    const float* x   = (const float*)d_in[0];
    const float* W   = (const float*)d_in[1];
    const int*   lbl = (const int*)d_in[2];
    float* out = (float*)d_out;

    const long long BC = (long long)Bm * (long long)Cn;   // 102,400,000
    const bool cos_in_out = ((long long)out_size >= BC);

    normalize_x_kernel<<<Bm, 128>>>(x);
    wnorm_kernel<<<(Cn + 255) / 256, 256>>>(W);

    // grid: x = M-blocks (8, fast-moving), y = N-blocks (782) -> W tiles L2-shared
    dim3 gg(Bm / BMT, (Cn + BNT - 1) / BNT);   // (8, 782)
    gemm_cos_kernel<<<gg, 256>>>(W, cos_in_out ? out : nullptr);

    if (!cos_in_out) {
        if (out_size >= 1) loss_kernel<<<1, Bm>>>(nullptr, lbl, out);
    } else if ((long long)out_size >= BC + 1) {
        loss_kernel<<<1, Bm>>>(out, lbl, out + BC);
    }
}

// round 13
// speedup vs baseline: 1.8142x; 1.4102x over previous
#include <cuda_runtime.h>
#include <cuda_fp16.h>
#include <cstdint>
#include <cstddef>

// ---------------- problem constants ----------------
static constexpr int Bm = 1024;     // batch rows
static constexpr int Dk = 512;      // feature dim (K)
static constexpr int Cn = 100000;   // classes (N)
static constexpr float S_s = 30.0f;
static constexpr float M_m = 0.4f;

// GEMM config
#define BMT 128
#define BNT 128
#define BKT 32
static constexpr int NCHUNK = Dk / BKT;   // 16
static constexpr int STAGES = 4;
static constexpr int A_STAGE = BMT * BKT * 2;   // 8192 B
static constexpr int B_STAGE = BKT * BNT * 2;   // 8192 B
static constexpr int SMEM_BYTES = STAGES * (A_STAGE + B_STAGE);  // 65536

// ---------------- device scratch (no runtime allocation allowed) ----------------
__device__ __half g_Xh[Bm * Dk];                      // normalized x, fp16
__device__ __half g_Wh[(size_t)Dk * (size_t)Cn];      // W converted to fp16
__device__ float g_winv[Cn];                          // 1 / ||W[:,c]||
__device__ float g_rowsum[Bm];                        // sum_c exp(S*cos)
__device__ float g_cos_scratch[(size_t)Bm * (size_t)Cn]; // fallback cossim store

// ---------------- helpers ----------------
__device__ __forceinline__ uint32_t f2h2(float a, float b) {
    __half2 h = __floats2half2_rn(a, b);
    return *reinterpret_cast<uint32_t*>(&h);
}

__device__ __forceinline__ void mma16(float* d, const uint32_t* a, const uint32_t* b) {
    asm volatile(
        "mma.sync.aligned.m16n8k16.row.col.f32.f16.f16.f32 "
        "{%0,%1,%2,%3}, {%4,%5,%6,%7}, {%8,%9}, {%0,%1,%2,%3};\n"
        : "+f"(d[0]), "+f"(d[1]), "+f"(d[2]), "+f"(d[3])
        : "r"(a[0]), "r"(a[1]), "r"(a[2]), "r"(a[3]), "r"(b[0]), "r"(b[1]));
}
__device__ __forceinline__ void ldsm4(uint32_t* r, uint32_t addr) {
    asm volatile("ldmatrix.sync.aligned.m8n8.x4.shared.b16 {%0,%1,%2,%3}, [%4];"
                 : "=r"(r[0]), "=r"(r[1]), "=r"(r[2]), "=r"(r[3]) : "r"(addr));
}
__device__ __forceinline__ void ldsm2t(uint32_t* r, uint32_t addr) {
    asm volatile("ldmatrix.sync.aligned.m8n8.x2.trans.shared.b16 {%0,%1}, [%2];"
                 : "=r"(r[0]), "=r"(r[1]) : "r"(addr));
}
__device__ __forceinline__ void cp16(uint32_t smem_dst, const void* gsrc) {
    asm volatile("cp.async.cg.shared.global [%0], [%1], 16;"
                 :: "r"(smem_dst), "l"(gsrc) : "memory");
}
__device__ __forceinline__ void cp_commit() {
    asm volatile("cp.async.commit_group;" ::: "memory");
}
template <int N>
__device__ __forceinline__ void cp_wait() {
    asm volatile("cp.async.wait_group %0;" :: "n"(N) : "memory");
}

// swizzled byte offsets inside the smem tiles (16B cell granularity)
// A tile: 128 rows x 32 halfs (64B/row = 4 cells): cell ^= (row>>1)&3
__device__ __forceinline__ int a_byte(int r, int c) {
    return r * 64 + ((c ^ ((r >> 1) & 3)) << 4);
}
// B tile: 32 k-rows x 128 halfs (256B/row = 16 cells): cell ^= k&7
__device__ __forceinline__ int b_byte(int k, int c) {
    return k * 256 + ((c ^ (k & 7)) << 4);
}

// ---------------- kernel 1: L2-normalize rows of x -> fp16; zero rowsum ----------
__global__ void normalize_x_kernel(const float* __restrict__ x) {
    const int b = blockIdx.x;           // 1024 blocks
    const int t = threadIdx.x;          // 128 threads
    float4 v = reinterpret_cast<const float4*>(x + (size_t)b * Dk)[t];
    float ss = v.x * v.x + v.y * v.y + v.z * v.z + v.w * v.w;
    #pragma unroll
    for (int o = 16; o > 0; o >>= 1) ss += __shfl_xor_sync(0xffffffffu, ss, o);
    __shared__ float ws[4];
    if ((t & 31) == 0) ws[t >> 5] = ss;
    __syncthreads();
    const float tot = ws[0] + ws[1] + ws[2] + ws[3];
    const float inv = 1.0f / fmaxf(sqrtf(tot), 1e-12f);
    uint2 st;
    st.x = f2h2(v.x * inv, v.y * inv);
    st.y = f2h2(v.z * inv, v.w * inv);
    reinterpret_cast<uint2*>(g_Xh + (size_t)b * Dk)[t] = st;
    if (t == 0) g_rowsum[b] = 0.0f;
}

// ---------------- kernel 2: W column inv-norms + fp16 conversion (one pass) -------
__global__ void wprep_kernel(const float* __restrict__ Wp) {
    const int c0 = (blockIdx.x * blockDim.x + threadIdx.x) * 2;   // 2 columns/thread
    if (c0 >= Cn) return;
    float s0 = 0.0f, s1 = 0.0f;
    #pragma unroll 4
    for (int d = 0; d < Dk; ++d) {
        const float2 w = *reinterpret_cast<const float2*>(Wp + (size_t)d * Cn + c0);
        s0 = fmaf(w.x, w.x, s0);
        s1 = fmaf(w.y, w.y, s1);
        *reinterpret_cast<uint32_t*>(g_Wh + (size_t)d * Cn + c0) = f2h2(w.x, w.y);
    }
    g_winv[c0]     = 1.0f / fmaxf(sqrtf(s0), 1e-12f);
    g_winv[c0 + 1] = 1.0f / fmaxf(sqrtf(s1), 1e-12f);
}

// ---------------- kernel 3: fp16 GEMM, cp.async 4-stage + fused epilogue ----------
__global__ void __launch_bounds__(256, 2)
gemm_cos_kernel(float* __restrict__ outp) {
    extern __shared__ __align__(128) uint8_t smem[];
    uint8_t* As = smem;                       // STAGES x 8KB
    uint8_t* Bs = smem + STAGES * A_STAGE;    // STAGES x 8KB

    float* __restrict__ outc = outp ? outp : g_cos_scratch;

    const int tid  = threadIdx.x;
    const int lane = tid & 31;
    const int g    = lane >> 2;
    const int t    = lane & 3;
    const int warp = tid >> 5;
    const int wm   = warp & 1;    // 2 warps in M (64 rows each)
    const int wn   = warp >> 1;   // 4 warps in N (32 cols each)
    const int bN   = blockIdx.y * BNT;
    const int bM   = blockIdx.x * BMT;

    const uint32_t sA0 = (uint32_t)__cvta_generic_to_shared(As);
    const uint32_t sB0 = (uint32_t)__cvta_generic_to_shared(Bs);

    // ---- load coordinates (cp.async, 16B granules) ----
    // A: thread owns row (tid>>1), cells ac0, ac0+1 (8 halfs each)
    const int arow = tid >> 1;
    const int ac0  = (tid & 1) * 2;
    // B: thread owns k-row (tid>>3), cells bc0, bc0+1
    const int bk   = tid >> 3;
    const int bc0  = (tid & 7) * 2;
    const int bn0  = bN + bc0 * 8;
    const bool bvalid = (bn0 + 16 <= Cn);   // Cn % 16 == 0 -> all-or-nothing

    const __half* Abase = g_Xh + (size_t)(bM + arow) * Dk + ac0 * 8;

    auto issue_stage = [&](int s) {
        const int buf = s % STAGES;
        const int kc  = s * BKT;
        const uint32_t dA = sA0 + buf * A_STAGE;
        const uint32_t dB = sB0 + buf * B_STAGE;
        cp16(dA + a_byte(arow, ac0),     Abase + kc);
        cp16(dA + a_byte(arow, ac0 + 1), Abase + kc + 8);
        if (bvalid) {
            const __half* Bp = g_Wh + (size_t)(kc + bk) * Cn + bn0;
            cp16(dB + b_byte(bk, bc0),     Bp);
            cp16(dB + b_byte(bk, bc0 + 1), Bp + 8);
        } else {
            const uint4 z = make_uint4(0, 0, 0, 0);
            *reinterpret_cast<uint4*>(Bs + buf * B_STAGE + b_byte(bk, bc0))     = z;
            *reinterpret_cast<uint4*>(Bs + buf * B_STAGE + b_byte(bk, bc0 + 1)) = z;
        }
    };

    float acc[4][4][4];
    #pragma unroll
    for (int i = 0; i < 4; ++i)
        #pragma unroll
        for (int j = 0; j < 4; ++j)
            #pragma unroll
            for (int k = 0; k < 4; ++k) acc[i][j][k] = 0.0f;

    // per-lane ldmatrix address components
    const int rl = lane & 15;     // row within 16-row tile
    const int cp = lane >> 4;     // k-half selector

    auto compute_chunk = [&](int buf) {
        const uint32_t sAb = sA0 + buf * A_STAGE;
        const uint32_t sBb = sB0 + buf * B_STAGE;
        #pragma unroll
        for (int ks = 0; ks < 2; ++ks) {
            uint32_t af[4][4];
            uint32_t bf[4][2];
            #pragma unroll
            for (int mt = 0; mt < 4; ++mt)
                ldsm4(af[mt], sAb + a_byte(wm * 64 + mt * 16 + rl, ks * 2 + cp));
            #pragma unroll
            for (int nt = 0; nt < 4; ++nt)
                ldsm2t(bf[nt], sBb + b_byte(ks * 16 + rl, wn * 4 + nt));
            #pragma unroll
            for (int mt = 0; mt < 4; ++mt)
                #pragma unroll
                for (int nt = 0; nt < 4; ++nt)
                    mma16(acc[mt][nt], af[mt], bf[nt]);
        }
    };

    // ---- 4-stage pipelined mainloop ----
    issue_stage(0); cp_commit();
    issue_stage(1); cp_commit();
    issue_stage(2); cp_commit();

    for (int it = 0; it < NCHUNK; ++it) {
        cp_wait<2>();
        __syncthreads();
        if (it + 3 < NCHUNK) issue_stage(it + 3);
        cp_commit();                 // empty groups at tail keep wait-depth math valid
        compute_chunk(it % STAGES);
    }

    // -------- fused epilogue: scale by 1/||w_c||, clip, store, accumulate exp-sums ----
    float rsum[4][2];
    #pragma unroll
    for (int mt = 0; mt < 4; ++mt) { rsum[mt][0] = 0.0f; rsum[mt][1] = 0.0f; }

    #pragma unroll
    for (int mt = 0; mt < 4; ++mt) {
        const int gr0 = bM + wm * 64 + mt * 16 + g;
        #pragma unroll
        for (int nt = 0; nt < 4; ++nt) {
            const int gc = bN + wn * 32 + nt * 8 + t * 2;
            if (gc < Cn) {
                const float iw0 = g_winv[gc];
                const float iw1 = g_winv[gc + 1];
                float c0 = fminf(fmaxf(acc[mt][nt][0] * iw0, -1.0f), 1.0f);
                float c1 = fminf(fmaxf(acc[mt][nt][1] * iw1, -1.0f), 1.0f);
                float c2 = fminf(fmaxf(acc[mt][nt][2] * iw0, -1.0f), 1.0f);
                float c3 = fminf(fmaxf(acc[mt][nt][3] * iw1, -1.0f), 1.0f);
                *reinterpret_cast<float2*>(&outc[(size_t)gr0 * Cn + gc]) = make_float2(c0, c1);
                *reinterpret_cast<float2*>(&outc[(size_t)(gr0 + 8) * Cn + gc]) = make_float2(c2, c3);
                rsum[mt][0] += __expf(S_s * c0) + __expf(S_s * c1);
                rsum[mt][1] += __expf(S_s * c2) + __expf(S_s * c3);
            }
        }
    }
    #pragma unroll
    for (int mt = 0; mt < 4; ++mt) {
        #pragma unroll
        for (int h = 0; h < 2; ++h) {
            float v = rsum[mt][h];
            v += __shfl_xor_sync(0xffffffffu, v, 1);
            v += __shfl_xor_sync(0xffffffffu, v, 2);
            if (t == 0) {
                const int gr = bM + wm * 64 + mt * 16 + g + h * 8;
                atomicAdd(&g_rowsum[gr], v);
            }
        }
    }
}

// ---------------- kernel 4: per-row loss, mean, scalar out ----------------
__global__ void loss_kernel(const float* __restrict__ cosp_param,
                            const int* __restrict__ lbl32,
                            float* __restrict__ loss_out) {
    const float* cosp = cosp_param ? cosp_param : g_cos_scratch;
    const int b = threadIdx.x;   // 1024 threads, one block

    __shared__ int nz;
    if (b == 0) nz = 0;
    __syncthreads();
    if (b < 512 && lbl32[2 * b + 1] != 0) atomicOr(&nz, 1);
    __syncthreads();

    int label;
    if (nz == 0) label = (int)(reinterpret_cast<const long long*>(lbl32)[b]);
    else         label = lbl32[b];

    const float tgt  = cosp[(size_t)b * Cn + label];
    const float excl = g_rowsum[b] - __expf(S_s * tgt);
    const float num  = S_s * (tgt - M_m);
    const float L    = num - logf(expf(num) + excl);

    float v = L;
    #pragma unroll
    for (int o = 16; o > 0; o >>= 1) v += __shfl_xor_sync(0xffffffffu, v, o);
    __shared__ float red[32];
    if ((b & 31) == 0) red[b >> 5] = v;
    __syncthreads();
    if (b < 32) {
        float w = red[b];
        #pragma unroll
        for (int o = 16; o > 0; o >>= 1) w += __shfl_xor_sync(0xffffffffu, w, o);
        if (b == 0) loss_out[0] = -(w / (float)Bm);
    }
}

// ---------------- launch ----------------
extern "C" void kernel_launch(void* const* d_in, const int* in_sizes, int n_in,
                              void* d_out, int out_size) {
    const float* x   = (const float*)d_in[0];
    const float* W   = (const float*)d_in[1];
    const int*   lbl = (const int*)d_in[2];
    float* out = (float*)d_out;

    const long long BC = (long long)Bm * (long long)Cn;   // 102,400,000
    const bool cos_in_out = ((long long)out_size >= BC);

    static bool attr_set = false;
    if (!attr_set) {
        cudaFuncSetAttribute(gemm_cos_kernel,
                             cudaFuncAttributeMaxDynamicSharedMemorySize, SMEM_BYTES);
        attr_set = true;
    }

    normalize_x_kernel<<<Bm, 128>>>(x);
    wprep_kernel<<<(Cn / 2 + 255) / 256, 256>>>(W);

    // grid: x = M-blocks (8, fast-moving), y = N-blocks (782) -> W tiles L2-shared
    dim3 gg(Bm / BMT, (Cn + BNT - 1) / BNT);   // (8, 782)
    gemm_cos_kernel<<<gg, 256, SMEM_BYTES>>>(cos_in_out ? out : nullptr);

    if (!cos_in_out) {
        if (out_size >= 1) loss_kernel<<<1, Bm>>>(nullptr, lbl, out);
    } else if ((long long)out_size >= BC + 1) {
        loss_kernel<<<1, Bm>>>(out, lbl, out + BC);
    }
}

// round 14
// speedup vs baseline: 1.9751x; 1.0887x over previous
#include <cuda_runtime.h>
#include <cuda_fp16.h>
#include <cstdint>
#include <cstddef>

// ---------------- problem constants ----------------
static constexpr int Bm = 1024;     // batch rows
static constexpr int Dk = 512;      // feature dim (K)
static constexpr int Cn = 100000;   // classes (N)
static constexpr float S_s = 30.0f;
static constexpr float M_m = 0.4f;

// GEMM config
#define BMT 128
#define BNT 128
#define BKT 32
static constexpr int NCHUNK = Dk / BKT;   // 16
static constexpr int STAGES = 4;
static constexpr int A_STAGE = BMT * BKT * 2;   // 8192 B
static constexpr int B_STAGE = BKT * BNT * 2;   // 8192 B
static constexpr int SMEM_BYTES = STAGES * (A_STAGE + B_STAGE);  // 65536

// ---------------- device scratch (no runtime allocation allowed) ----------------
__device__ __half g_Xh[Bm * Dk];                      // normalized x, fp16
__device__ __half g_Wh[(size_t)Dk * (size_t)Cn];      // W converted to fp16
__device__ float g_winv[Cn];                          // 1 / ||W[:,c]||
__device__ float g_rowsum[Bm];                        // sum_c exp(S*cos)
__device__ float g_lsum;                              // loss partial-sum accumulator
__device__ int   g_ldone;                             // loss block ticket counter
__device__ float g_cos_scratch[(size_t)Bm * (size_t)Cn]; // fallback cossim store

// ---------------- helpers ----------------
__device__ __forceinline__ uint32_t f2h2(float a, float b) {
    __half2 h = __floats2half2_rn(a, b);
    return *reinterpret_cast<uint32_t*>(&h);
}

__device__ __forceinline__ void mma16(float* d, const uint32_t* a, const uint32_t* b) {
    asm volatile(
        "mma.sync.aligned.m16n8k16.row.col.f32.f16.f16.f32 "
        "{%0,%1,%2,%3}, {%4,%5,%6,%7}, {%8,%9}, {%0,%1,%2,%3};\n"
        : "+f"(d[0]), "+f"(d[1]), "+f"(d[2]), "+f"(d[3])
        : "r"(a[0]), "r"(a[1]), "r"(a[2]), "r"(a[3]), "r"(b[0]), "r"(b[1]));
}
__device__ __forceinline__ void ldsm4(uint32_t* r, uint32_t addr) {
    asm volatile("ldmatrix.sync.aligned.m8n8.x4.shared.b16 {%0,%1,%2,%3}, [%4];"
                 : "=r"(r[0]), "=r"(r[1]), "=r"(r[2]), "=r"(r[3]) : "r"(addr));
}
__device__ __forceinline__ void ldsm4t(uint32_t* r, uint32_t addr) {
    asm volatile("ldmatrix.sync.aligned.m8n8.x4.trans.shared.b16 {%0,%1,%2,%3}, [%4];"
                 : "=r"(r[0]), "=r"(r[1]), "=r"(r[2]), "=r"(r[3]) : "r"(addr));
}
__device__ __forceinline__ void cp16(uint32_t smem_dst, const void* gsrc) {
    asm volatile("cp.async.cg.shared.global [%0], [%1], 16;"
                 :: "r"(smem_dst), "l"(gsrc) : "memory");
}
__device__ __forceinline__ void cp_commit() {
    asm volatile("cp.async.commit_group;" ::: "memory");
}
template <int N>
__device__ __forceinline__ void cp_wait() {
    asm volatile("cp.async.wait_group %0;" :: "n"(N) : "memory");
}

// swizzled byte offsets inside the smem tiles (16B cell granularity)
// A tile: 128 rows x 32 halfs (64B/row = 4 cells): cell ^= (row>>1)&3
__device__ __forceinline__ int a_byte(int r, int c) {
    return r * 64 + ((c ^ ((r >> 1) & 3)) << 4);
}
// B tile: 32 k-rows x 128 halfs (256B/row = 16 cells): cell ^= k&7
__device__ __forceinline__ int b_byte(int k, int c) {
    return k * 256 + ((c ^ (k & 7)) << 4);
}

// ---------------- kernel 1: L2-normalize rows of x -> fp16; zero accumulators ------
__global__ void normalize_x_kernel(const float* __restrict__ x) {
    const int b = blockIdx.x;           // 1024 blocks
    const int t = threadIdx.x;          // 128 threads
    float4 v = reinterpret_cast<const float4*>(x + (size_t)b * Dk)[t];
    float ss = v.x * v.x + v.y * v.y + v.z * v.z + v.w * v.w;
    #pragma unroll
    for (int o = 16; o > 0; o >>= 1) ss += __shfl_xor_sync(0xffffffffu, ss, o);
    __shared__ float ws[4];
    if ((t & 31) == 0) ws[t >> 5] = ss;
    __syncthreads();
    const float tot = ws[0] + ws[1] + ws[2] + ws[3];
    const float inv = 1.0f / fmaxf(sqrtf(tot), 1e-12f);
    uint2 st;
    st.x = f2h2(v.x * inv, v.y * inv);
    st.y = f2h2(v.z * inv, v.w * inv);
    reinterpret_cast<uint2*>(g_Xh + (size_t)b * Dk)[t] = st;
    if (t == 0) g_rowsum[b] = 0.0f;
    if (b == 0 && t == 0) { g_lsum = 0.0f; g_ldone = 0; }
}

// ---------------- kernel 2: W column inv-norms + fp16 conversion (one pass) -------
__global__ void wprep_kernel(const float* __restrict__ Wp) {
    const int c0 = (blockIdx.x * blockDim.x + threadIdx.x) * 4;   // 4 columns/thread
    if (c0 >= Cn) return;
    float s0 = 0.0f, s1 = 0.0f, s2 = 0.0f, s3 = 0.0f;
    #pragma unroll 4
    for (int d = 0; d < Dk; ++d) {
        const float4 w = *reinterpret_cast<const float4*>(Wp + (size_t)d * Cn + c0);
        s0 = fmaf(w.x, w.x, s0);
        s1 = fmaf(w.y, w.y, s1);
        s2 = fmaf(w.z, w.z, s2);
        s3 = fmaf(w.w, w.w, s3);
        uint2 h;
        h.x = f2h2(w.x, w.y);
        h.y = f2h2(w.z, w.w);
        *reinterpret_cast<uint2*>(g_Wh + (size_t)d * Cn + c0) = h;
    }
    float4 o;
    o.x = 1.0f / fmaxf(sqrtf(s0), 1e-12f);
    o.y = 1.0f / fmaxf(sqrtf(s1), 1e-12f);
    o.z = 1.0f / fmaxf(sqrtf(s2), 1e-12f);
    o.w = 1.0f / fmaxf(sqrtf(s3), 1e-12f);
    *reinterpret_cast<float4*>(g_winv + c0) = o;
}

// ---------------- kernel 3: fp16 GEMM, cp.async 4-stage + fused epilogue ----------
__global__ void __launch_bounds__(256, 2)
gemm_cos_kernel(float* __restrict__ outp) {
    extern __shared__ __align__(128) uint8_t smem[];
    uint8_t* As = smem;                       // STAGES x 8KB
    uint8_t* Bs = smem + STAGES * A_STAGE;    // STAGES x 8KB

    float* __restrict__ outc = outp ? outp : g_cos_scratch;

    const int tid  = threadIdx.x;
    const int lane = tid & 31;
    const int g    = lane >> 2;
    const int t    = lane & 3;
    const int warp = tid >> 5;
    const int wm   = warp & 1;    // 2 warps in M (64 rows each)
    const int wn   = warp >> 1;   // 4 warps in N (32 cols each)
    const int bN   = blockIdx.y * BNT;
    const int bM   = blockIdx.x * BMT;

    const uint32_t sA0 = (uint32_t)__cvta_generic_to_shared(As);
    const uint32_t sB0 = (uint32_t)__cvta_generic_to_shared(Bs);

    // ---- load coordinates (cp.async, 16B granules) ----
    const int arow = tid >> 1;
    const int ac0  = (tid & 1) * 2;
    const int bk   = tid >> 3;
    const int bc0  = (tid & 7) * 2;
    const int bn0  = bN + bc0 * 8;
    const bool bvalid = (bn0 + 16 <= Cn);   // Cn % 16 == 0 -> all-or-nothing

    const __half* Abase = g_Xh + (size_t)(bM + arow) * Dk + ac0 * 8;

    auto issue_stage = [&](int s) {
        const int buf = s % STAGES;
        const int kc  = s * BKT;
        const uint32_t dA = sA0 + buf * A_STAGE;
        const uint32_t dB = sB0 + buf * B_STAGE;
        cp16(dA + a_byte(arow, ac0),     Abase + kc);
        cp16(dA + a_byte(arow, ac0 + 1), Abase + kc + 8);
        if (bvalid) {
            const __half* Bp = g_Wh + (size_t)(kc + bk) * Cn + bn0;
            cp16(dB + b_byte(bk, bc0),     Bp);
            cp16(dB + b_byte(bk, bc0 + 1), Bp + 8);
        } else {
            const uint4 z = make_uint4(0, 0, 0, 0);
            *reinterpret_cast<uint4*>(Bs + buf * B_STAGE + b_byte(bk, bc0))     = z;
            *reinterpret_cast<uint4*>(Bs + buf * B_STAGE + b_byte(bk, bc0 + 1)) = z;
        }
    };

    float acc[4][4][4];
    #pragma unroll
    for (int i = 0; i < 4; ++i)
        #pragma unroll
        for (int j = 0; j < 4; ++j)
            #pragma unroll
            for (int k = 0; k < 4; ++k) acc[i][j][k] = 0.0f;

    // per-lane ldmatrix address components
    const int rl = lane & 15;     // row within 16-row tile
    const int cp = lane >> 4;     // cell selector (second half of lanes)

    auto compute_chunk = [&](int buf) {
        const uint32_t sAb = sA0 + buf * A_STAGE;
        const uint32_t sBb = sB0 + buf * B_STAGE;
        #pragma unroll
        for (int ks = 0; ks < 2; ++ks) {
            uint32_t af[4][4];
            uint32_t bf[4][2];
            #pragma unroll
            for (int mt = 0; mt < 4; ++mt)
                ldsm4(af[mt], sAb + a_byte(wm * 64 + mt * 16 + rl, ks * 2 + cp));
            // x4.trans: lanes 0-15 -> n-cell (wn*4+2j), lanes 16-31 -> (wn*4+2j+1)
            #pragma unroll
            for (int j = 0; j < 2; ++j)
                ldsm4t(&bf[2 * j][0], sBb + b_byte(ks * 16 + rl, wn * 4 + 2 * j + cp));
            #pragma unroll
            for (int mt = 0; mt < 4; ++mt)
                #pragma unroll
                for (int nt = 0; nt < 4; ++nt)
                    mma16(acc[mt][nt], af[mt], bf[nt]);
        }
    };

    // ---- 4-stage pipelined mainloop (fully unrolled: compile-time stage indices) ----
    issue_stage(0); cp_commit();
    issue_stage(1); cp_commit();
    issue_stage(2); cp_commit();

    #pragma unroll
    for (int it = 0; it < NCHUNK; ++it) {
        cp_wait<2>();
        __syncthreads();
        if (it + 3 < NCHUNK) issue_stage(it + 3);
        cp_commit();                 // empty groups at tail keep wait-depth math valid
        compute_chunk(it % STAGES);
    }

    // -------- fused epilogue: scale by 1/||w_c||, clip, store, accumulate exp-sums ----
    float rsum[4][2];
    #pragma unroll
    for (int mt = 0; mt < 4; ++mt) { rsum[mt][0] = 0.0f; rsum[mt][1] = 0.0f; }

    #pragma unroll
    for (int mt = 0; mt < 4; ++mt) {
        const int gr0 = bM + wm * 64 + mt * 16 + g;
        #pragma unroll
        for (int nt = 0; nt < 4; ++nt) {
            const int gc = bN + wn * 32 + nt * 8 + t * 2;
            if (gc < Cn) {
                const float iw0 = g_winv[gc];
                const float iw1 = g_winv[gc + 1];
                float c0 = fminf(fmaxf(acc[mt][nt][0] * iw0, -1.0f), 1.0f);
                float c1 = fminf(fmaxf(acc[mt][nt][1] * iw1, -1.0f), 1.0f);
                float c2 = fminf(fmaxf(acc[mt][nt][2] * iw0, -1.0f), 1.0f);
                float c3 = fminf(fmaxf(acc[mt][nt][3] * iw1, -1.0f), 1.0f);
                *reinterpret_cast<float2*>(&outc[(size_t)gr0 * Cn + gc]) = make_float2(c0, c1);
                *reinterpret_cast<float2*>(&outc[(size_t)(gr0 + 8) * Cn + gc]) = make_float2(c2, c3);
                rsum[mt][0] += __expf(S_s * c0) + __expf(S_s * c1);
                rsum[mt][1] += __expf(S_s * c2) + __expf(S_s * c3);
            }
        }
    }
    #pragma unroll
    for (int mt = 0; mt < 4; ++mt) {
        #pragma unroll
        for (int h = 0; h < 2; ++h) {
            float v = rsum[mt][h];
            v += __shfl_xor_sync(0xffffffffu, v, 1);
            v += __shfl_xor_sync(0xffffffffu, v, 2);
            if (t == 0) {
                const int gr = bM + wm * 64 + mt * 16 + g + h * 8;
                atomicAdd(&g_rowsum[gr], v);
            }
        }
    }
}

// ---------------- kernel 4: parallel per-row loss -> atomic sum -> last block writes --
__global__ void loss_kernel(const float* __restrict__ cosp_param,
                            const int* __restrict__ lbl32,
                            float* __restrict__ loss_out) {
    const float* cosp = cosp_param ? cosp_param : g_cos_scratch;
    const int b = blockIdx.x * 128 + threadIdx.x;   // grid 8 x 128 threads

    // detect label dtype within this block's slice (int64 labels -> high words all 0)
    __shared__ int nz;
    if (threadIdx.x == 0) nz = 0;
    __syncthreads();
    if (lbl32[2 * b + 1] != 0) atomicOr(&nz, 1);
    __syncthreads();

    int label;
    if (nz == 0) label = (int)(reinterpret_cast<const long long*>(lbl32)[b]);
    else         label = lbl32[b];

    const float tgt  = cosp[(size_t)b * Cn + label];
    const float excl = g_rowsum[b] - __expf(S_s * tgt);
    const float num  = S_s * (tgt - M_m);
    const float L    = num - logf(expf(num) + excl);

    float v = L;
    #pragma unroll
    for (int o = 16; o > 0; o >>= 1) v += __shfl_xor_sync(0xffffffffu, v, o);
    __shared__ float red[4];
    if ((threadIdx.x & 31) == 0) red[threadIdx.x >> 5] = v;
    __syncthreads();
    if (threadIdx.x == 0) {
        const float s = red[0] + red[1] + red[2] + red[3];
        atomicAdd(&g_lsum, s);
        __threadfence();
        const int tkt = atomicAdd(&g_ldone, 1);
        if (tkt == (int)gridDim.x - 1) {
            const float total = atomicAdd(&g_lsum, 0.0f);   // ordered read after all adds
            loss_out[0] = -(total / (float)Bm);
        }
    }
}

// ---------------- launch ----------------
extern "C" void kernel_launch(void* const* d_in, const int* in_sizes, int n_in,
                              void* d_out, int out_size) {
    const float* x   = (const float*)d_in[0];
    const float* W   = (const float*)d_in[1];
    const int*   lbl = (const int*)d_in[2];
    float* out = (float*)d_out;

    const long long BC = (long long)Bm * (long long)Cn;   // 102,400,000
    const bool cos_in_out = ((long long)out_size >= BC);

    static bool attr_set = false;
    if (!attr_set) {
        cudaFuncSetAttribute(gemm_cos_kernel,
                             cudaFuncAttributeMaxDynamicSharedMemorySize, SMEM_BYTES);
        attr_set = true;
    }

    normalize_x_kernel<<<Bm, 128>>>(x);
    wprep_kernel<<<(Cn / 4 + 255) / 256, 256>>>(W);

    // grid: x = M-blocks (8, fast-moving), y = N-blocks (782) -> W tiles L2-shared
    dim3 gg(Bm / BMT, (Cn + BNT - 1) / BNT);   // (8, 782)
    gemm_cos_kernel<<<gg, 256, SMEM_BYTES>>>(cos_in_out ? out : nullptr);

    if (!cos_in_out) {
        if (out_size >= 1) loss_kernel<<<8, 128>>>(nullptr, lbl, out);
    } else if ((long long)out_size >= BC + 1) {
        loss_kernel<<<8, 128>>>(out, lbl, out + BC);
    }
}